// round 2
// baseline (speedup 1.0000x reference)
#include <cuda_runtime.h>
#include <math_constants.h>

// Problem constants (fixed by the reference setup)
#define SEQ    2048
#define DMODEL 1024
#define NHEADS 16
#define DEPTH  64
#define BATCH  2
#define MROWS  (BATCH * SEQ)   // 4096

// Scratch (allocation-free rule: __device__ globals)
__device__ float g_q[MROWS * DMODEL];
__device__ float g_k[MROWS * DMODEL];
__device__ float g_v[MROWS * DMODEL];
__device__ float g_attn[MROWS * DMODEL];

// ---------------------------------------------------------------------------
// SGEMM: C[M,N] = alpha * A[M,K] @ B[K,N], all row-major, dims divisible.
// 128x128 tile, BK=8, 256 threads, 8x8 per-thread microtile.
// ---------------------------------------------------------------------------
#define BM 128
#define BN 128
#define BKK 8

__global__ __launch_bounds__(256) void sgemm_kernel(
    const float* __restrict__ A, const float* __restrict__ B,
    float* __restrict__ C, int M, int N, int K, float alpha)
{
    __shared__ float As[BKK][BM];
    __shared__ float Bs[BKK][BN];

    const int tid = threadIdx.x;
    const int blockRow = blockIdx.y * BM;
    const int blockCol = blockIdx.x * BN;

    // A-tile load: 128 rows x 8 cols, one float4 per thread
    const int aRow = tid >> 1;
    const int aCol = (tid & 1) * 4;
    // B-tile load: 8 rows x 128 cols, one float4 per thread
    const int bRow = tid >> 5;
    const int bCol = (tid & 31) * 4;

    const int tRow = (tid >> 4) * 8;
    const int tCol = (tid & 15) * 8;

    float acc[8][8];
    #pragma unroll
    for (int i = 0; i < 8; i++)
        #pragma unroll
        for (int j = 0; j < 8; j++)
            acc[i][j] = 0.0f;

    for (int k0 = 0; k0 < K; k0 += BKK) {
        float4 a = *(const float4*)(A + (size_t)(blockRow + aRow) * K + k0 + aCol);
        As[aCol + 0][aRow] = a.x;
        As[aCol + 1][aRow] = a.y;
        As[aCol + 2][aRow] = a.z;
        As[aCol + 3][aRow] = a.w;
        float4 b = *(const float4*)(B + (size_t)(k0 + bRow) * N + blockCol + bCol);
        *(float4*)(&Bs[bRow][bCol]) = b;
        __syncthreads();

        #pragma unroll
        for (int k = 0; k < BKK; k++) {
            float ra[8], rb[8];
            *(float4*)(ra)     = *(const float4*)(&As[k][tRow]);
            *(float4*)(ra + 4) = *(const float4*)(&As[k][tRow + 4]);
            *(float4*)(rb)     = *(const float4*)(&Bs[k][tCol]);
            *(float4*)(rb + 4) = *(const float4*)(&Bs[k][tCol + 4]);
            #pragma unroll
            for (int i = 0; i < 8; i++)
                #pragma unroll
                for (int j = 0; j < 8; j++)
                    acc[i][j] = fmaf(ra[i], rb[j], acc[i][j]);
        }
        __syncthreads();
    }

    #pragma unroll
    for (int i = 0; i < 8; i++) {
        #pragma unroll
        for (int jj = 0; jj < 2; jj++) {
            float4 v;
            v.x = alpha * acc[i][jj * 4 + 0];
            v.y = alpha * acc[i][jj * 4 + 1];
            v.z = alpha * acc[i][jj * 4 + 2];
            v.w = alpha * acc[i][jj * 4 + 3];
            *(float4*)(C + (size_t)(blockRow + tRow + i) * N + blockCol + tCol + jj * 4) = v;
        }
    }
}

// ---------------------------------------------------------------------------
// Flash attention (fp32, online softmax).
// Grid: (SEQ/BQ, NHEADS, BATCH). Block: 128 threads, each owns one query row.
// K/V tiles of BK=32 rows staged in SMEM; per-thread scores stored in a
// private SMEM column (Ss[j][t]) to keep register count and code size down.
// Output written in [B, S, H*DEPTH] layout = reference's merged-head layout.
// ---------------------------------------------------------------------------
#define BQ 128
#define BKT 32

__global__ __launch_bounds__(128) void flash_kernel(
    const float* __restrict__ Q, const float* __restrict__ Kg,
    const float* __restrict__ Vg, const float* __restrict__ bias,
    float* __restrict__ O)
{
    __shared__ float Ks[BKT][DEPTH];
    __shared__ float Vs[BKT][DEPTH];
    __shared__ float Ss[BKT][BQ];

    const int t = threadIdx.x;
    const int h = blockIdx.y;
    const int b = blockIdx.z;
    const int qr = blockIdx.x * BQ + t;      // query position within sequence

    // Load this thread's query row into registers (16 float4 = 64 floats)
    const float* qptr = Q + ((size_t)(b * SEQ + qr)) * DMODEL + h * DEPTH;
    float4 qv[16];
    #pragma unroll
    for (int i = 0; i < 16; i++) qv[i] = ((const float4*)qptr)[i];

    float4 o4[16];
    #pragma unroll
    for (int i = 0; i < 16; i++) o4[i] = make_float4(0.f, 0.f, 0.f, 0.f);
    float m = -CUDART_INF_F;
    float l = 0.0f;

    const float* biasrow = bias + (size_t)qr * SEQ;

    for (int kt = 0; kt < SEQ; kt += BKT) {
        // Cooperative coalesced load of K and V tiles (512 float4 each)
        #pragma unroll
        for (int i = 0; i < 4; i++) {
            int idx = t + i * 128;          // float4 index in [0, 512)
            int row = idx >> 4;             // 16 float4 per 64-float row
            int col = idx & 15;
            const float* kbase = Kg + ((size_t)(b * SEQ + kt + row)) * DMODEL + h * DEPTH;
            const float* vbase = Vg + ((size_t)(b * SEQ + kt + row)) * DMODEL + h * DEPTH;
            ((float4*)&Ks[row][0])[col] = ((const float4*)kbase)[col];
            ((float4*)&Vs[row][0])[col] = ((const float4*)vbase)[col];
        }
        __syncthreads();

        // Scores: s[j] = q . K[j]  (each thread does its own row)
        #pragma unroll 4
        for (int j = 0; j < BKT; j++) {
            float accx = 0.f, accy = 0.f, accz = 0.f, accw = 0.f;
            #pragma unroll
            for (int i = 0; i < 16; i++) {
                float4 kv = ((const float4*)&Ks[j][0])[i];
                accx = fmaf(qv[i].x, kv.x, accx);
                accy = fmaf(qv[i].y, kv.y, accy);
                accz = fmaf(qv[i].z, kv.z, accz);
                accw = fmaf(qv[i].w, kv.w, accw);
            }
            Ss[j][t] = (accx + accy) + (accz + accw);
        }

        // Add bias, find tile max
        float tmax = -CUDART_INF_F;
        #pragma unroll
        for (int jj = 0; jj < BKT / 4; jj++) {
            float4 bv = *(const float4*)(biasrow + kt + jj * 4);
            float s0 = Ss[jj * 4 + 0][t] + bv.x;
            float s1 = Ss[jj * 4 + 1][t] + bv.y;
            float s2 = Ss[jj * 4 + 2][t] + bv.z;
            float s3 = Ss[jj * 4 + 3][t] + bv.w;
            Ss[jj * 4 + 0][t] = s0;
            Ss[jj * 4 + 1][t] = s1;
            Ss[jj * 4 + 2][t] = s2;
            Ss[jj * 4 + 3][t] = s3;
            tmax = fmaxf(tmax, fmaxf(fmaxf(s0, s1), fmaxf(s2, s3)));
        }

        // Online softmax rescale
        float newm = fmaxf(m, tmax);
        float corr = __expf(m - newm);
        l *= corr;
        #pragma unroll
        for (int i = 0; i < 16; i++) {
            o4[i].x *= corr; o4[i].y *= corr; o4[i].z *= corr; o4[i].w *= corr;
        }
        float lad = 0.f;
        #pragma unroll
        for (int j = 0; j < BKT; j++) {
            float p = __expf(Ss[j][t] - newm);
            lad += p;
            Ss[j][t] = p;
        }
        l += lad;
        m = newm;

        // Accumulate O += p * V
        #pragma unroll 4
        for (int j = 0; j < BKT; j++) {
            float p = Ss[j][t];
            #pragma unroll
            for (int i = 0; i < 16; i++) {
                float4 vv = ((const float4*)&Vs[j][0])[i];
                o4[i].x = fmaf(p, vv.x, o4[i].x);
                o4[i].y = fmaf(p, vv.y, o4[i].y);
                o4[i].z = fmaf(p, vv.z, o4[i].z);
                o4[i].w = fmaf(p, vv.w, o4[i].w);
            }
        }
        __syncthreads();   // protect Ks/Vs before next tile load
    }

    const float inv = 1.0f / l;
    float* optr = O + ((size_t)(b * SEQ + qr)) * DMODEL + h * DEPTH;
    #pragma unroll
    for (int i = 0; i < 16; i++) {
        float4 ov;
        ov.x = o4[i].x * inv; ov.y = o4[i].y * inv;
        ov.z = o4[i].z * inv; ov.w = o4[i].w * inv;
        ((float4*)optr)[i] = ov;
    }
}

// ---------------------------------------------------------------------------
// Launch
// ---------------------------------------------------------------------------
extern "C" void kernel_launch(void* const* d_in, const int* in_sizes, int n_in,
                              void* d_out, int out_size)
{
    const float* x    = (const float*)d_in[0];
    const float* y    = (const float*)d_in[1];
    const float* bias = (const float*)d_in[2];
    const float* Wq   = (const float*)d_in[3];
    const float* Wk   = (const float*)d_in[4];
    const float* Wv   = (const float*)d_in[5];
    const float* Wo   = (const float*)d_in[6];
    float* out = (float*)d_out;

    float *q, *k, *v, *attn;
    cudaGetSymbolAddress((void**)&q,    g_q);
    cudaGetSymbolAddress((void**)&k,    g_k);
    cudaGetSymbolAddress((void**)&v,    g_v);
    cudaGetSymbolAddress((void**)&attn, g_attn);

    dim3 ggrid(DMODEL / BN, MROWS / BM);   // (8, 32)
    dim3 gblock(256);

    // q = (x @ Wq) * sqrt(depth) = * 8
    sgemm_kernel<<<ggrid, gblock, 0, 0>>>(x, Wq, q, MROWS, DMODEL, DMODEL, 8.0f);
    sgemm_kernel<<<ggrid, gblock, 0, 0>>>(y, Wk, k, MROWS, DMODEL, DMODEL, 1.0f);
    sgemm_kernel<<<ggrid, gblock, 0, 0>>>(y, Wv, v, MROWS, DMODEL, DMODEL, 1.0f);

    dim3 fgrid(SEQ / BQ, NHEADS, BATCH);   // (16, 16, 2)
    flash_kernel<<<fgrid, 128, 0, 0>>>(q, k, v, bias, attn);

    sgemm_kernel<<<ggrid, gblock, 0, 0>>>(attn, Wo, out, MROWS, DMODEL, DMODEL, 1.0f);
}